// round 7
// baseline (speedup 1.0000x reference)
#include <cuda_runtime.h>
#include <math.h>
#include <cstdint>

// Problem constants
constexpr int B = 8;
constexpr int T = 4096;
constexpr int C = 8;
constexpr int E = 1024;   // MAX_EVENTS
constexpr int D = 512;
constexpr int F = 2048;
constexpr int NL = 4;
constexpr int NH = 8;
constexpr int DH = 64;

// ---------------- device scratch (no allocation allowed) ----------------
__device__ float g_rows[B * E * 11];
__device__ float g_mask[B * E];
__device__ float g_h[(size_t)B * E * D];
__device__ float g_z[(size_t)B * E * D];
__device__ float g_q[(size_t)B * E * D];
__device__ float g_k[(size_t)B * E * D];
__device__ float g_v[(size_t)B * E * D];
__device__ float g_o[(size_t)B * E * D];
__device__ float g_f[(size_t)B * E * F];
// transposed weights (K-major, [N,K]), pre-rounded to tf32:
// qkvT interleaved per layer [3*D, D], then oT, w1T, w2T
__device__ float g_wT[12582912];

constexpr size_t OFF_QKV = 0;                    // 4 * 3*D*D = 3145728
constexpr size_t OFF_OT  = 3145728;              // 4 * D*D   = 1048576
constexpr size_t OFF_W1T = 4194304;              // 4 * D*F   = 4194304
constexpr size_t OFF_W2T = 8388608;              // 4 * F*D   = 4194304

// ================= PTX helpers =================
__device__ __forceinline__ uint32_t smem_u32(const void* p) {
    uint32_t a;
    asm("{ .reg .u64 t; cvta.to.shared.u64 t, %1; cvt.u32.u64 %0, t; }" : "=r"(a) : "l"(p));
    return a;
}
__device__ __forceinline__ void cpasync16(uint32_t dst, const void* src) {
    asm volatile("cp.async.cg.shared.global [%0], [%1], 16;" :: "r"(dst), "l"(src));
}
#define CP_COMMIT() asm volatile("cp.async.commit_group;" ::: "memory")
#define CP_WAIT(n)  asm volatile("cp.async.wait_group %0;" :: "n"(n) : "memory")

__device__ __forceinline__ uint32_t f2tf32(float f) {
    uint32_t r;
    asm("cvt.rna.tf32.f32 %0, %1;" : "=r"(r) : "f"(f));
    return r;
}
__device__ __forceinline__ float roundtf(float f) { return __uint_as_float(f2tf32(f)); }

__device__ __forceinline__ void mma_tf32(float& c0, float& c1, float& c2, float& c3,
                                         uint32_t a0, uint32_t a1, uint32_t a2, uint32_t a3,
                                         uint32_t b0, uint32_t b1) {
    asm volatile(
        "mma.sync.aligned.m16n8k8.row.col.f32.tf32.tf32.f32 "
        "{%0,%1,%2,%3}, {%4,%5,%6,%7}, {%8,%9}, {%0,%1,%2,%3};"
        : "+f"(c0), "+f"(c1), "+f"(c2), "+f"(c3)
        : "r"(a0), "r"(a1), "r"(a2), "r"(a3), "r"(b0), "r"(b1));
}

// ---------------- GELU (tanh approximation, matches jax.nn.gelu default) ----
__device__ __forceinline__ float gelu_f(float v) {
    const float c = 0.7978845608028654f;
    float t = tanhf(c * (v + 0.044715f * v * v * v));
    return 0.5f * v * (1.f + t);
}

// ================= tf32 mma.sync GEMM =======================================
// C[M,N] = A[M,K] @ W[K,N] with WT = W^T given as [N,K] (K-major).
// Inputs A and WT are PRE-ROUNDED to tf32 -> no cvt in the mainloop.
// Block tile 128x128, BK=32, 256 threads (8 warps, 2x4 grid of 64x32 warp
// tiles) -> 4 warps per SMSP for latency hiding. Double-buffered cp.async.
// SPLIT3: N=1536 QKV-fused; output segment s -> C0/C1/C2 (stride 512); segs 0,1
// (q,k) are rounded at write, seg 2 (v) kept fp32 for the attention V-split.
constexpr int LDP = 36;                      // padded row length (floats)
constexpr int OPBUF = 128 * LDP;             // one operand tile in floats (4608)
constexpr int BUFF = 2 * OPBUF;              // A + B per buffer (9216 floats)
constexpr int GSMEM = 2 * BUFF * 4;          // 73728 bytes

template <bool BIAS, bool GELU_, bool RES, bool RND, bool SPLIT3>
__global__ __launch_bounds__(256)
void tgemm_kernel(const float* __restrict__ A, const float* __restrict__ WT,
                  const float* __restrict__ bias,
                  float* __restrict__ C0, float* __restrict__ C1, float* __restrict__ C2,
                  int M, int N, int K) {
    extern __shared__ float sm[];
    const uint32_t sb = smem_u32(sm);
    const int tid = threadIdx.x;
    const int wid = tid >> 5, lane = tid & 31;
    const int g = lane >> 2, q = lane & 3;
    const int wm = (wid & 1) * 64;            // warp m offset (2 rows of warps)
    const int wn = (wid >> 1) * 32;           // warp n offset (4 cols of warps)
    const int bn = blockIdx.x;
    const int n0 = bn * 128;                  // global n (WT row, bias offset)
    const int m0 = blockIdx.y * 128;

    float* Cout = C0;
    int c0 = n0, nOut = N;
    bool rnd = RND;
    if (SPLIT3) {
        const int seg = bn >> 2;
        Cout = (seg == 0) ? C0 : ((seg == 1) ? C1 : C2);
        c0 = (bn & 3) * 128;
        nOut = 512;
        rnd = (seg < 2);
    }

    float acc[4][4][4];
#pragma unroll
    for (int i = 0; i < 4; i++)
#pragma unroll
        for (int j = 0; j < 4; j++)
#pragma unroll
            for (int k = 0; k < 4; k++) acc[i][j][k] = 0.f;

    auto load_tile = [&](int bf, int i) {
        const int k0 = i * 32;
        const float* Ap = A + (size_t)m0 * K + k0;
        const float* Bp = WT + (size_t)n0 * K + k0;
        const uint32_t baseA = sb + (uint32_t)(bf * BUFF) * 4;
        const uint32_t baseB = baseA + OPBUF * 4;
#pragma unroll
        for (int j = 0; j < 4; j++) {
            const int ch = j * 256 + tid;          // 0..1023
            const int row = ch >> 3, cc = ch & 7;
            const uint32_t so = (uint32_t)(row * LDP + cc * 4) * 4;
            cpasync16(baseA + so, Ap + (size_t)row * K + cc * 4);
            cpasync16(baseB + so, Bp + (size_t)row * K + cc * 4);
        }
        CP_COMMIT();
    };

    const int NK = K >> 5;
    load_tile(0, 0);
    for (int i = 0; i < NK; i++) {
        if (i + 1 < NK) {
            load_tile((i + 1) & 1, i + 1);
            CP_WAIT(1);
        } else {
            CP_WAIT(0);
        }
        __syncthreads();

        const float* sA = sm + (i & 1) * BUFF;
        const float* sB = sA + OPBUF;
#pragma unroll
        for (int ks = 0; ks < 4; ks++) {
            const int kb = ks * 8;
            uint32_t af[4][4];
#pragma unroll
            for (int mt = 0; mt < 4; mt++) {
                const int r0 = wm + mt * 16 + g;
                af[mt][0] = __float_as_uint(sA[(r0)     * LDP + kb + q]);
                af[mt][1] = __float_as_uint(sA[(r0 + 8) * LDP + kb + q]);
                af[mt][2] = __float_as_uint(sA[(r0)     * LDP + kb + q + 4]);
                af[mt][3] = __float_as_uint(sA[(r0 + 8) * LDP + kb + q + 4]);
            }
            uint32_t bfr[4][2];
#pragma unroll
            for (int nt = 0; nt < 4; nt++) {
                const int cc = wn + nt * 8 + g;
                bfr[nt][0] = __float_as_uint(sB[cc * LDP + kb + q]);
                bfr[nt][1] = __float_as_uint(sB[cc * LDP + kb + q + 4]);
            }
#pragma unroll
            for (int mt = 0; mt < 4; mt++)
#pragma unroll
                for (int nt = 0; nt < 4; nt++)
                    mma_tf32(acc[mt][nt][0], acc[mt][nt][1], acc[mt][nt][2], acc[mt][nt][3],
                             af[mt][0], af[mt][1], af[mt][2], af[mt][3],
                             bfr[nt][0], bfr[nt][1]);
        }
        __syncthreads();
    }

#pragma unroll
    for (int mt = 0; mt < 4; mt++) {
        const int r0 = m0 + wm + mt * 16 + g;
#pragma unroll
        for (int nt = 0; nt < 4; nt++) {
            const int cb = c0 + wn + nt * 8 + 2 * q;
            float2 v0 = make_float2(acc[mt][nt][0], acc[mt][nt][1]);
            float2 v1 = make_float2(acc[mt][nt][2], acc[mt][nt][3]);
            if (BIAS) {
                const float2 bb = *(const float2*)(bias + n0 + wn + nt * 8 + 2 * q);
                v0.x += bb.x; v0.y += bb.y; v1.x += bb.x; v1.y += bb.y;
            }
            if (GELU_) {
                v0.x = gelu_f(v0.x); v0.y = gelu_f(v0.y);
                v1.x = gelu_f(v1.x); v1.y = gelu_f(v1.y);
            }
            float* p0 = Cout + (size_t)r0 * nOut + cb;
            float* p1 = Cout + (size_t)(r0 + 8) * nOut + cb;
            if (RES) {
                const float2 o0 = *(const float2*)p0;
                const float2 o1 = *(const float2*)p1;
                v0.x += o0.x; v0.y += o0.y; v1.x += o1.x; v1.y += o1.y;
            }
            if (RND || SPLIT3) {
                if (rnd) {
                    v0.x = roundtf(v0.x); v0.y = roundtf(v0.y);
                    v1.x = roundtf(v1.x); v1.y = roundtf(v1.y);
                }
            }
            *(float2*)p0 = v0;
            *(float2*)p1 = v1;
        }
    }
}

// ================= tf32 mma flash attention =================================
// grid (E/64, NH, B), 128 threads (4 warps x 16 q-rows). K/V 64-key tiles,
// double-buffered cp.async. Q,K pre-rounded tf32 -> no cvt in score loop.
// PV: 3x tf32 split (hi*hi + hi*lo + lo*hi) on fp32 V -> ~fp32 precision.
constexpr int ALD = 68;                  // padded row (floats): 4g+q banks
constexpr int ATILE = 64 * ALD;          // 4352 floats
constexpr int ASMEM = (5 * ATILE + 128) * 4;   // QP + 2K + 2V + masks = 87552B

__global__ __launch_bounds__(128)
void attn_mma_kernel(const float* __restrict__ Qg, const float* __restrict__ Kg,
                     const float* __restrict__ Vg, const float* __restrict__ maskb,
                     float* __restrict__ O) {
    extern __shared__ float sm[];
    const uint32_t sb = smem_u32(sm);
    const int qb = blockIdx.x, hd = blockIdx.y, b = blockIdx.z;
    const int tid = threadIdx.x, wid = tid >> 5, lane = tid & 31;
    const int g = lane >> 2, q = lane & 3;
    const int wr = wid * 16;

    const size_t basekv = (size_t)(b * E) * D + hd * DH;

    auto load_kv = [&](int buf, int i) {
        const float* Kp = Kg + basekv + (size_t)(i * 64) * D;
        const float* Vp = Vg + basekv + (size_t)(i * 64) * D;
        const uint32_t sK = sb + (uint32_t)((1 + buf) * ATILE) * 4;
        const uint32_t sV = sb + (uint32_t)((3 + buf) * ATILE) * 4;
#pragma unroll
        for (int j = 0; j < 8; j++) {
            const int ch = j * 128 + tid;          // 1024 chunks: 64 rows x 16
            const int r = ch >> 4, c4 = ch & 15;
            const uint32_t off = (uint32_t)(r * ALD + c4 * 4) * 4;
            cpasync16(sK + off, Kp + (size_t)r * D + c4 * 4);
            cpasync16(sV + off, Vp + (size_t)r * D + c4 * 4);
        }
        if (tid < 16)
            cpasync16(sb + (uint32_t)(5 * ATILE + buf * 64 + tid * 4) * 4,
                      maskb + b * E + i * 64 + tid * 4);
        CP_COMMIT();
    };
    load_kv(0, 0);
    load_kv(1, 1);

    // Q tile (pre-scaled by 0.125 = 2^-3: keeps tf32-representability) -> sQP
    const size_t baseq = ((size_t)(b * E) + qb * 64) * D + hd * DH;
#pragma unroll
    for (int j = 0; j < 8; j++) {
        const int ch = j * 128 + tid;
        const int r = ch >> 4, c4 = ch & 15;
        float4 v = *(const float4*)(Qg + baseq + (size_t)r * D + c4 * 4);
        v.x *= 0.125f; v.y *= 0.125f; v.z *= 0.125f; v.w *= 0.125f;
        *(float4*)(sm + r * ALD + c4 * 4) = v;
    }
    __syncthreads();

    // Q fragments in registers for the whole kernel (own warp rows only)
    uint32_t qa[8][4];
#pragma unroll
    for (int ks = 0; ks < 8; ks++) {
        const int kb = ks * 8;
        qa[ks][0] = __float_as_uint(sm[(wr + g) * ALD + kb + q]);
        qa[ks][1] = __float_as_uint(sm[(wr + g + 8) * ALD + kb + q]);
        qa[ks][2] = __float_as_uint(sm[(wr + g) * ALD + kb + q + 4]);
        qa[ks][3] = __float_as_uint(sm[(wr + g + 8) * ALD + kb + q + 4]);
    }
    __syncwarp();

    float m0 = -1e30f, m1 = -1e30f, l0 = 0.f, l1 = 0.f;
    float oacc[8][4];
#pragma unroll
    for (int nf = 0; nf < 8; nf++)
#pragma unroll
        for (int k = 0; k < 4; k++) oacc[nf][k] = 0.f;

    float* Prow0 = sm + (wr + g) * ALD;        // P reuses the Q smem region
    float* Prow1 = sm + (wr + g + 8) * ALD;

    for (int i = 0; i < 16; i++) {
        const int buf = i & 1;
        if (i < 15) { CP_WAIT(1); } else { CP_WAIT(0); }
        __syncthreads();
        const float* sKb = sm + (1 + buf) * ATILE;
        const float* sVb = sm + (3 + buf) * ATILE;
        const float* kmb = sm + 5 * ATILE + buf * 64;

        // ---- scores: S = Q K^T (1x tf32, operands pre-rounded) ----
        float sc[8][4];
#pragma unroll
        for (int nf = 0; nf < 8; nf++)
#pragma unroll
            for (int k = 0; k < 4; k++) sc[nf][k] = 0.f;
#pragma unroll
        for (int ks = 0; ks < 8; ks++) {
            const int kb = ks * 8;
#pragma unroll
            for (int nf = 0; nf < 8; nf++) {
                const uint32_t b0 = __float_as_uint(sKb[(nf * 8 + g) * ALD + kb + q]);
                const uint32_t b1 = __float_as_uint(sKb[(nf * 8 + g) * ALD + kb + q + 4]);
                mma_tf32(sc[nf][0], sc[nf][1], sc[nf][2], sc[nf][3],
                         qa[ks][0], qa[ks][1], qa[ks][2], qa[ks][3], b0, b1);
            }
        }

        // ---- mask + online softmax ----
        float mt0 = -1e30f, mt1 = -1e30f;
#pragma unroll
        for (int nf = 0; nf < 8; nf++) {
            const float mk0 = kmb[nf * 8 + 2 * q];
            const float mk1 = kmb[nf * 8 + 2 * q + 1];
            if (mk0 == 0.f) { sc[nf][0] = -1e9f; sc[nf][2] = -1e9f; }
            if (mk1 == 0.f) { sc[nf][1] = -1e9f; sc[nf][3] = -1e9f; }
            mt0 = fmaxf(mt0, fmaxf(sc[nf][0], sc[nf][1]));
            mt1 = fmaxf(mt1, fmaxf(sc[nf][2], sc[nf][3]));
        }
        mt0 = fmaxf(mt0, __shfl_xor_sync(0xFFFFFFFFu, mt0, 1));
        mt0 = fmaxf(mt0, __shfl_xor_sync(0xFFFFFFFFu, mt0, 2));
        mt1 = fmaxf(mt1, __shfl_xor_sync(0xFFFFFFFFu, mt1, 1));
        mt1 = fmaxf(mt1, __shfl_xor_sync(0xFFFFFFFFu, mt1, 2));
        const float mn0 = fmaxf(m0, mt0), mn1 = fmaxf(m1, mt1);
        const float al0 = __expf(m0 - mn0), al1 = __expf(m1 - mn1);
        m0 = mn0; m1 = mn1;

        float ps0 = 0.f, ps1 = 0.f;
#pragma unroll
        for (int nf = 0; nf < 8; nf++) {
            const float p0 = __expf(sc[nf][0] - mn0);
            const float p1 = __expf(sc[nf][1] - mn0);
            const float p2 = __expf(sc[nf][2] - mn1);
            const float p3 = __expf(sc[nf][3] - mn1);
            ps0 += p0 + p1; ps1 += p2 + p3;
            Prow0[nf * 8 + 2 * q] = p0; Prow0[nf * 8 + 2 * q + 1] = p1;
            Prow1[nf * 8 + 2 * q] = p2; Prow1[nf * 8 + 2 * q + 1] = p3;
            oacc[nf][0] *= al0; oacc[nf][1] *= al0;
            oacc[nf][2] *= al1; oacc[nf][3] *= al1;
        }
        ps0 += __shfl_xor_sync(0xFFFFFFFFu, ps0, 1);
        ps0 += __shfl_xor_sync(0xFFFFFFFFu, ps0, 2);
        ps1 += __shfl_xor_sync(0xFFFFFFFFu, ps1, 1);
        ps1 += __shfl_xor_sync(0xFFFFFFFFu, ps1, 2);
        l0 = l0 * al0 + ps0; l1 = l1 * al1 + ps1;
        __syncwarp();   // P visible within warp (A-frags read only own warp rows)

        // ---- O += P V (3x tf32: hi*hi + hi*lo + lo*hi) ----
#pragma unroll
        for (int ks = 0; ks < 8; ks++) {
            const int kb = ks * 8;
            const float f0 = Prow0[kb + q];
            const float f1 = Prow1[kb + q];
            const float f2 = Prow0[kb + q + 4];
            const float f3 = Prow1[kb + q + 4];
            uint32_t ah[4], alo[4];
            ah[0] = f2tf32(f0); alo[0] = f2tf32(f0 - __uint_as_float(ah[0]));
            ah[1] = f2tf32(f1); alo[1] = f2tf32(f1 - __uint_as_float(ah[1]));
            ah[2] = f2tf32(f2); alo[2] = f2tf32(f2 - __uint_as_float(ah[2]));
            ah[3] = f2tf32(f3); alo[3] = f2tf32(f3 - __uint_as_float(ah[3]));
#pragma unroll
            for (int nf = 0; nf < 8; nf++) {
                const float v0 = sVb[(kb + q) * ALD + nf * 8 + g];
                const float v1 = sVb[(kb + q + 4) * ALD + nf * 8 + g];
                const uint32_t vh0 = f2tf32(v0), vh1 = f2tf32(v1);
                const uint32_t vl0 = f2tf32(v0 - __uint_as_float(vh0));
                const uint32_t vl1 = f2tf32(v1 - __uint_as_float(vh1));
                mma_tf32(oacc[nf][0], oacc[nf][1], oacc[nf][2], oacc[nf][3],
                         ah[0], ah[1], ah[2], ah[3], vh0, vh1);
                mma_tf32(oacc[nf][0], oacc[nf][1], oacc[nf][2], oacc[nf][3],
                         ah[0], ah[1], ah[2], ah[3], vl0, vl1);
                mma_tf32(oacc[nf][0], oacc[nf][1], oacc[nf][2], oacc[nf][3],
                         alo[0], alo[1], alo[2], alo[3], vh0, vh1);
            }
        }
        __syncthreads();              // everyone done with this K/V buffer
        if (i + 2 < 16) load_kv(buf, i + 2);
    }

    // O pre-rounded to tf32 (consumed only by the WO GEMM)
    const float il0 = 1.f / l0, il1 = 1.f / l1;
    float* Op0 = O + ((size_t)(b * E) + qb * 64 + wr + g) * D + hd * DH;
    float* Op1 = Op0 + (size_t)8 * D;
#pragma unroll
    for (int nf = 0; nf < 8; nf++) {
        *(float2*)(Op0 + nf * 8 + 2 * q) =
            make_float2(roundtf(oacc[nf][0] * il0), roundtf(oacc[nf][1] * il0));
        *(float2*)(Op1 + nf * 8 + 2 * q) =
            make_float2(roundtf(oacc[nf][2] * il1), roundtf(oacc[nf][3] * il1));
    }
}

// ======== weight transpose: in [K,N] -> out [N,K] tf32-rounded, per layer ====
__global__ void transpose_kernel(const float* __restrict__ in, float* __restrict__ out,
                                 int K, int N, int in_z, int out_z) {
    __shared__ float t[32][33];
    const float* ip = in + (size_t)blockIdx.z * in_z;
    float* op = out + (size_t)blockIdx.z * out_z;
    const int n0 = blockIdx.x * 32, k0 = blockIdx.y * 32;
    const int tx = threadIdx.x, ty = threadIdx.y;   // 32 x 8
#pragma unroll
    for (int j = 0; j < 32; j += 8) t[ty + j][tx] = ip[(size_t)(k0 + ty + j) * N + n0 + tx];
    __syncthreads();
#pragma unroll
    for (int j = 0; j < 32; j += 8)
        op[(size_t)(n0 + ty + j) * K + k0 + tx] = roundtf(t[tx][ty + j]);
}

// ---------------- event extraction ----------------
__global__ void build_events_kernel(const float* __restrict__ x,
                                    float* __restrict__ rows,
                                    float* __restrict__ maskb) {
    const int b = blockIdx.x;
    const int tid = threadIdx.x;                 // 256 threads
    __shared__ unsigned char sx[T];
    __shared__ int partial[256];

    for (int i = tid; i < E * 11; i += 256) rows[(size_t)b * E * 11 + i] = 0.f;
    for (int i = tid; i < E; i += 256) maskb[b * E + i] = 0.f;

    const float* xb = x + (size_t)b * T * C;
    for (int t = tid; t < T; t += 256) {
        unsigned v = 0;
#pragma unroll
        for (int c = 0; c < C; c++) v |= (xb[(size_t)t * C + c] > 0.5f) ? (1u << c) : 0u;
        sx[t] = (unsigned char)v;
    }
    __syncthreads();

    const int t0 = tid * 16;
    unsigned char prev = (t0 == 0) ? (unsigned char)(~sx[0]) : sx[t0 - 1];
    unsigned char smloc[16];
    int cnt = 0;
#pragma unroll
    for (int i = 0; i < 16; i++) {
        unsigned char cur = sx[t0 + i];
        smloc[i] = (unsigned char)(cur ^ prev);
        prev = cur;
        cnt += __popc((unsigned)smloc[i]);
    }
    partial[tid] = cnt;
    __syncthreads();
    if (tid == 0) {
        int run = 0;
        for (int i = 0; i < 256; i++) { int tmp = partial[i]; partial[i] = run; run += tmp; }
    }
    __syncthreads();

    int e = partial[tid];
    for (int i = 0; i < 16; i++) {
        const int t = t0 + i;
        unsigned m = smloc[i];
        while (m) {
            const int c = __ffs(m) - 1;
            m &= (m - 1);
            if (e < E) {
                const int v = (sx[t] >> c) & 1;
                int tt = t + 1;
                while (tt < T && (((sx[tt] >> c) & 1) == v)) tt++;
                float* r = rows + ((size_t)b * E + e) * 11;
                r[c] = 1.f;
                r[8] = (float)v;
                r[9] = (float)t / (float)(T - 1);
                r[10] = (float)(tt - t) / (float)T;
                maskb[b * E + e] = 1.f;
            }
            e++;
        }
    }
}

// ---------------- input projection (K=11) ----------------
__global__ void proj_kernel(const float* __restrict__ rows,
                            const float* __restrict__ pw,
                            const float* __restrict__ pb,
                            float* __restrict__ h) {
    const int be = blockIdx.x;
    __shared__ float r[11];
    if (threadIdx.x < 11) r[threadIdx.x] = rows[(size_t)be * 11 + threadIdx.x];
    __syncthreads();
    const int d = threadIdx.x;
    float acc = pb[d];
#pragma unroll
    for (int j = 0; j < 11; j++) acc += r[j] * pw[j * D + d];
    h[(size_t)be * D + d] = acc;
}

// ---------------- LayerNorm: warp per row, tf32-rounded output -------------
__global__ __launch_bounds__(256)
void ln_kernel(const float* __restrict__ h, const float* __restrict__ g,
               const float* __restrict__ bb, float* __restrict__ z) {
    const int row = blockIdx.x * 8 + (threadIdx.x >> 5);
    const int lane = threadIdx.x & 31;
    const float* hr = h + (size_t)row * D;

    float4 v[4];
    float s = 0.f, s2 = 0.f;
#pragma unroll
    for (int i = 0; i < 4; i++) {
        v[i] = *(const float4*)(hr + i * 128 + lane * 4);
        s += v[i].x + v[i].y + v[i].z + v[i].w;
        s2 += v[i].x * v[i].x + v[i].y * v[i].y + v[i].z * v[i].z + v[i].w * v[i].w;
    }
#pragma unroll
    for (int o = 16; o; o >>= 1) {
        s += __shfl_xor_sync(0xFFFFFFFFu, s, o);
        s2 += __shfl_xor_sync(0xFFFFFFFFu, s2, o);
    }
    const float mean = s * (1.f / D);
    const float var = s2 * (1.f / D) - mean * mean;
    const float inv = rsqrtf(var + 1e-5f);

    float* zr = z + (size_t)row * D;
#pragma unroll
    for (int i = 0; i < 4; i++) {
        const int cc = i * 128 + lane * 4;
        const float4 gg = *(const float4*)(g + cc);
        const float4 bv = *(const float4*)(bb + cc);
        float4 o;
        o.x = roundtf((v[i].x - mean) * inv * gg.x + bv.x);
        o.y = roundtf((v[i].y - mean) * inv * gg.y + bv.y);
        o.z = roundtf((v[i].z - mean) * inv * gg.z + bv.z);
        o.w = roundtf((v[i].w - mean) * inv * gg.w + bv.w);
        *(float4*)(zr + cc) = o;
    }
}

// ---------------- masked mean pooling ----------------
__global__ void pool_kernel(const float* __restrict__ z,
                            const float* __restrict__ maskb,
                            float* __restrict__ out) {
    const int b = blockIdx.x;
    const int d = threadIdx.x;
    float s = 0.f, cnt = 0.f;
    for (int e = 0; e < E; e++) {
        const float mk = maskb[b * E + e];
        cnt += mk;
        s += z[((size_t)b * E + e) * D + d] * mk;
    }
    out[(size_t)b * D + d] = s / fmaxf(cnt, 1.f);
}

// ---------------- launch ----------------
extern "C" void kernel_launch(void* const* d_in, const int* in_sizes, int n_in,
                              void* d_out, int out_size) {
    const float* x      = (const float*)d_in[0];
    const float* proj_w = (const float*)d_in[1];
    const float* proj_b = (const float*)d_in[2];
    const float* wq     = (const float*)d_in[3];
    const float* wk     = (const float*)d_in[4];
    const float* wv     = (const float*)d_in[5];
    const float* wo     = (const float*)d_in[6];
    const float* ln1_g  = (const float*)d_in[7];
    const float* ln1_b  = (const float*)d_in[8];
    const float* w1     = (const float*)d_in[9];
    const float* b1     = (const float*)d_in[10];
    const float* w2     = (const float*)d_in[11];
    const float* b2     = (const float*)d_in[12];
    const float* ln2_g  = (const float*)d_in[13];
    const float* ln2_b  = (const float*)d_in[14];
    const float* lnf_g  = (const float*)d_in[15];
    const float* lnf_b  = (const float*)d_in[16];
    float* out = (float*)d_out;

    float *p_rows, *p_mask, *p_h, *p_z, *p_q, *p_k, *p_v, *p_o, *p_f, *p_wT;
    cudaGetSymbolAddress((void**)&p_rows, g_rows);
    cudaGetSymbolAddress((void**)&p_mask, g_mask);
    cudaGetSymbolAddress((void**)&p_h, g_h);
    cudaGetSymbolAddress((void**)&p_z, g_z);
    cudaGetSymbolAddress((void**)&p_q, g_q);
    cudaGetSymbolAddress((void**)&p_k, g_k);
    cudaGetSymbolAddress((void**)&p_v, g_v);
    cudaGetSymbolAddress((void**)&p_o, g_o);
    cudaGetSymbolAddress((void**)&p_f, g_f);
    cudaGetSymbolAddress((void**)&p_wT, g_wT);

    static bool attr_set = false;
    if (!attr_set) {
        cudaFuncSetAttribute(tgemm_kernel<false, false, false, true, true>,  cudaFuncAttributeMaxDynamicSharedMemorySize, GSMEM);
        cudaFuncSetAttribute(tgemm_kernel<false, false, true, false, false>, cudaFuncAttributeMaxDynamicSharedMemorySize, GSMEM);
        cudaFuncSetAttribute(tgemm_kernel<true, true, false, true, false>,   cudaFuncAttributeMaxDynamicSharedMemorySize, GSMEM);
        cudaFuncSetAttribute(tgemm_kernel<true, false, true, false, false>,  cudaFuncAttributeMaxDynamicSharedMemorySize, GSMEM);
        cudaFuncSetAttribute(attn_mma_kernel, cudaFuncAttributeMaxDynamicSharedMemorySize, ASMEM);
        attr_set = true;
    }

    const int M = B * E;                       // 8192
    const dim3 gQKV(12, M / 128);              // fused QKV: N=1536
    const dim3 gD(D / 128, M / 128);           // (4, 64)
    const dim3 gF(F / 128, M / 128);           // (16, 64)
    const dim3 tb(32, 8);

    // transpose all weights into K-major tf32-rounded scratch
    transpose_kernel<<<dim3(D / 32, D / 32, NL), tb>>>(wq, p_wT + OFF_QKV,             D, D, D * D, 3 * D * D);
    transpose_kernel<<<dim3(D / 32, D / 32, NL), tb>>>(wk, p_wT + OFF_QKV + D * D,     D, D, D * D, 3 * D * D);
    transpose_kernel<<<dim3(D / 32, D / 32, NL), tb>>>(wv, p_wT + OFF_QKV + 2 * D * D, D, D, D * D, 3 * D * D);
    transpose_kernel<<<dim3(D / 32, D / 32, NL), tb>>>(wo, p_wT + OFF_OT,  D, D, D * D, D * D);
    transpose_kernel<<<dim3(F / 32, D / 32, NL), tb>>>(w1, p_wT + OFF_W1T, D, F, D * F, D * F);
    transpose_kernel<<<dim3(D / 32, F / 32, NL), tb>>>(w2, p_wT + OFF_W2T, F, D, F * D, F * D);

    build_events_kernel<<<B, 256>>>(x, p_rows, p_mask);
    proj_kernel<<<M, 512>>>(p_rows, proj_w, proj_b, p_h);

    for (int l = 0; l < NL; l++) {
        const float* qkvT = p_wT + OFF_QKV + (size_t)l * 3 * D * D;
        const float* woT  = p_wT + OFF_OT  + (size_t)l * D * D;
        const float* w1T  = p_wT + OFF_W1T + (size_t)l * D * F;
        const float* w2T  = p_wT + OFF_W2T + (size_t)l * D * F;

        ln_kernel<<<M / 8, 256>>>(p_h, ln1_g + l * D, ln1_b + l * D, p_z);
        tgemm_kernel<false, false, false, true, true><<<gQKV, 256, GSMEM>>>(
            p_z, qkvT, nullptr, p_q, p_k, p_v, M, 3 * D, D);
        attn_mma_kernel<<<dim3(E / 64, NH, B), 128, ASMEM>>>(p_q, p_k, p_v, p_mask, p_o);
        tgemm_kernel<false, false, true, false, false><<<gD, 256, GSMEM>>>(
            p_o, woT, nullptr, p_h, nullptr, nullptr, M, D, D);

        ln_kernel<<<M / 8, 256>>>(p_h, ln2_g + l * D, ln2_b + l * D, p_z);
        tgemm_kernel<true, true, false, true, false><<<gF, 256, GSMEM>>>(
            p_z, w1T, b1 + (size_t)l * F, p_f, nullptr, nullptr, M, F, D);
        tgemm_kernel<true, false, true, false, false><<<gD, 256, GSMEM>>>(
            p_f, w2T, b2 + (size_t)l * D, p_h, nullptr, nullptr, M, D, F);
    }

    ln_kernel<<<M / 8, 256>>>(p_h, lnf_g, lnf_b, p_z);
    pool_kernel<<<B, D>>>(p_z, p_mask, out);
}

// round 8
// speedup vs baseline: 1.1133x; 1.1133x over previous
#include <cuda_runtime.h>
#include <math.h>
#include <cstdint>

// Problem constants
constexpr int B = 8;
constexpr int T = 4096;
constexpr int C = 8;
constexpr int E = 1024;   // MAX_EVENTS
constexpr int D = 512;
constexpr int F = 2048;
constexpr int NL = 4;
constexpr int NH = 8;
constexpr int DH = 64;

// k-dim permutation within 8-groups: sigma(k) = (k%4)*2 + k/4.
// Applied to every tf32 GEMM contraction dim at the producer so fragment
// pairs {k=q, k=q+4} sit adjacent in memory -> LDS.64 fragment loads.

// ---------------- device scratch (no allocation allowed) ----------------
__device__ float g_rows[B * E * 11];
__device__ float g_mask[B * E];
__device__ float g_h[(size_t)B * E * D];
__device__ float g_z[(size_t)B * E * D];
__device__ float g_q[(size_t)B * E * D];
__device__ float g_k[(size_t)B * E * D];
__device__ float g_v[(size_t)B * E * D];
__device__ float g_o[(size_t)B * E * D];
__device__ float g_f[(size_t)B * E * F];
// transposed weights (K-major, [N,K]), tf32-rounded, k-permuted
__device__ float g_wT[12582912];

constexpr size_t OFF_QKV = 0;                    // 4 * 3*D*D = 3145728
constexpr size_t OFF_OT  = 3145728;              // 4 * D*D   = 1048576
constexpr size_t OFF_W1T = 4194304;              // 4 * D*F   = 4194304
constexpr size_t OFF_W2T = 8388608;              // 4 * F*D   = 4194304

// ================= PTX helpers =================
__device__ __forceinline__ uint32_t smem_u32(const void* p) {
    uint32_t a;
    asm("{ .reg .u64 t; cvta.to.shared.u64 t, %1; cvt.u32.u64 %0, t; }" : "=r"(a) : "l"(p));
    return a;
}
__device__ __forceinline__ void cpasync16(uint32_t dst, const void* src) {
    asm volatile("cp.async.cg.shared.global [%0], [%1], 16;" :: "r"(dst), "l"(src));
}
#define CP_COMMIT() asm volatile("cp.async.commit_group;" ::: "memory")
#define CP_WAIT(n)  asm volatile("cp.async.wait_group %0;" :: "n"(n) : "memory")

__device__ __forceinline__ uint32_t f2tf32(float f) {
    uint32_t r;
    asm("cvt.rna.tf32.f32 %0, %1;" : "=r"(r) : "f"(f));
    return r;
}
__device__ __forceinline__ float roundtf(float f) { return __uint_as_float(f2tf32(f)); }

__device__ __forceinline__ void mma_tf32(float& c0, float& c1, float& c2, float& c3,
                                         uint32_t a0, uint32_t a1, uint32_t a2, uint32_t a3,
                                         uint32_t b0, uint32_t b1) {
    asm volatile(
        "mma.sync.aligned.m16n8k8.row.col.f32.tf32.tf32.f32 "
        "{%0,%1,%2,%3}, {%4,%5,%6,%7}, {%8,%9}, {%0,%1,%2,%3};"
        : "+f"(c0), "+f"(c1), "+f"(c2), "+f"(c3)
        : "r"(a0), "r"(a1), "r"(a2), "r"(a3), "r"(b0), "r"(b1));
}

// ---------------- GELU (tanh approximation, matches jax.nn.gelu default) ----
__device__ __forceinline__ float gelu_f(float v) {
    const float c = 0.7978845608028654f;
    float t = tanhf(c * (v + 0.044715f * v * v * v));
    return 0.5f * v * (1.f + t);
}

// ================= tf32 mma.sync GEMM =======================================
// C[M,N] = A[M,K] @ W[K,N], WT = W^T [N,K] K-major; A and WT tf32-rounded and
// k-permuted -> fragment loads are conflict-free LDS.64, no cvt in mainloop.
// Block tile 128x128, BK=32, 128 threads (4 warps, 2x2 of 64x64 warp tiles).
// PERM(=RND) outputs: tf32-rounded + k-permuted (feeds another GEMM/attention).
constexpr int LDP = 40;                      // padded row: (40g+2q) banks
constexpr int OPBUF = 128 * LDP;             // one operand tile (5120 floats)
constexpr int BUFF = 2 * OPBUF;              // A + B per buffer
constexpr int GSMEM = 2 * BUFF * 4;          // 81920 bytes

template <bool BIAS, bool GELU_, bool RES, bool RND, bool SPLIT3>
__global__ __launch_bounds__(128)
void tgemm_kernel(const float* __restrict__ A, const float* __restrict__ WT,
                  const float* __restrict__ bias,
                  float* __restrict__ C0, float* __restrict__ C1, float* __restrict__ C2,
                  int M, int N, int K) {
    extern __shared__ float sm[];
    const uint32_t sb = smem_u32(sm);
    const int tid = threadIdx.x;
    const int wid = tid >> 5, lane = tid & 31;
    const int g = lane >> 2, q = lane & 3;
    const int wm = (wid & 1) * 64;
    const int wn = (wid >> 1) * 64;
    const int bn = blockIdx.x;
    const int n0 = bn * 128;                  // global n (WT row, bias offset)
    const int m0 = blockIdx.y * 128;

    float* Cout = C0;
    int c0 = n0, nOut = N;
    bool rnd = RND;
    if (SPLIT3) {
        const int seg = bn >> 2;
        Cout = (seg == 0) ? C0 : ((seg == 1) ? C1 : C2);
        c0 = (bn & 3) * 128;
        nOut = 512;
        rnd = (seg < 2);
    }

    float acc[4][8][4];
#pragma unroll
    for (int i = 0; i < 4; i++)
#pragma unroll
        for (int j = 0; j < 8; j++)
#pragma unroll
            for (int k = 0; k < 4; k++) acc[i][j][k] = 0.f;

    auto load_tile = [&](int bf, int i) {
        const int k0 = i * 32;
        const float* Ap = A + (size_t)m0 * K + k0;
        const float* Bp = WT + (size_t)n0 * K + k0;
        const uint32_t baseA = sb + (uint32_t)(bf * BUFF) * 4;
        const uint32_t baseB = baseA + OPBUF * 4;
#pragma unroll
        for (int j = 0; j < 8; j++) {
            const int ch = j * 128 + tid;          // 0..1023
            const int row = ch >> 3, cc = ch & 7;
            const uint32_t so = (uint32_t)(row * LDP + cc * 4) * 4;
            cpasync16(baseA + so, Ap + (size_t)row * K + cc * 4);
            cpasync16(baseB + so, Bp + (size_t)row * K + cc * 4);
        }
        CP_COMMIT();
    };

    const int NK = K >> 5;
    load_tile(0, 0);
    for (int i = 0; i < NK; i++) {
        if (i + 1 < NK) {
            load_tile((i + 1) & 1, i + 1);
            CP_WAIT(1);
        } else {
            CP_WAIT(0);
        }
        __syncthreads();

        const float* sA = sm + (i & 1) * BUFF;
        const float* sB = sA + OPBUF;
#pragma unroll
        for (int ks = 0; ks < 4; ks++) {
            const int kb = ks * 8 + 2 * q;        // physical pair start
            uint32_t af[4][4];
#pragma unroll
            for (int mt = 0; mt < 4; mt++) {
                const int r0 = wm + mt * 16 + g;
                const float2 lo = *(const float2*)(&sA[(r0)     * LDP + kb]);  // a0,a2
                const float2 hi = *(const float2*)(&sA[(r0 + 8) * LDP + kb]);  // a1,a3
                af[mt][0] = __float_as_uint(lo.x);
                af[mt][1] = __float_as_uint(hi.x);
                af[mt][2] = __float_as_uint(lo.y);
                af[mt][3] = __float_as_uint(hi.y);
            }
            uint32_t bfr[8][2];
#pragma unroll
            for (int nt = 0; nt < 8; nt++) {
                const int cc = wn + nt * 8 + g;
                const float2 bv = *(const float2*)(&sB[cc * LDP + kb]);        // b0,b1
                bfr[nt][0] = __float_as_uint(bv.x);
                bfr[nt][1] = __float_as_uint(bv.y);
            }
#pragma unroll
            for (int mt = 0; mt < 4; mt++)
#pragma unroll
                for (int nt = 0; nt < 8; nt++)
                    mma_tf32(acc[mt][nt][0], acc[mt][nt][1], acc[mt][nt][2], acc[mt][nt][3],
                             af[mt][0], af[mt][1], af[mt][2], af[mt][3],
                             bfr[nt][0], bfr[nt][1]);
        }
        __syncthreads();
    }

    const int pc = (q & 1) * 4 + (q >> 1);    // sigma(2q)
#pragma unroll
    for (int mt = 0; mt < 4; mt++) {
        const int r0 = m0 + wm + mt * 16 + g;
#pragma unroll
        for (int nt = 0; nt < 8; nt++) {
            const int cbase = c0 + wn + nt * 8;
            float2 v0 = make_float2(acc[mt][nt][0], acc[mt][nt][1]);
            float2 v1 = make_float2(acc[mt][nt][2], acc[mt][nt][3]);
            if (BIAS) {
                const float2 bb = *(const float2*)(bias + n0 + wn + nt * 8 + 2 * q);
                v0.x += bb.x; v0.y += bb.y; v1.x += bb.x; v1.y += bb.y;
            }
            if (GELU_) {
                v0.x = gelu_f(v0.x); v0.y = gelu_f(v0.y);
                v1.x = gelu_f(v1.x); v1.y = gelu_f(v1.y);
            }
            float* p0 = Cout + (size_t)r0 * nOut + cbase;
            float* p1 = Cout + (size_t)(r0 + 8) * nOut + cbase;
            if (RES) {
                const float2 o0 = *(const float2*)(p0 + 2 * q);
                const float2 o1 = *(const float2*)(p1 + 2 * q);
                v0.x += o0.x; v0.y += o0.y; v1.x += o1.x; v1.y += o1.y;
            }
            if (rnd) {
                // tf32-round + k-permute (output feeds a GEMM contraction)
                p0[pc] = roundtf(v0.x); p0[pc + 2] = roundtf(v0.y);
                p1[pc] = roundtf(v1.x); p1[pc + 2] = roundtf(v1.y);
            } else {
                *(float2*)(p0 + 2 * q) = v0;
                *(float2*)(p1 + 2 * q) = v1;
            }
        }
    }
}

// ================= tf32 mma flash attention =================================
// grid (E/64, NH, B), 128 threads. Q,K tf32-rounded + dh-permuted -> LDS.64
// fragment loads. PV: 3x tf32 split on fp32 V (unpermuted). P stored permuted.
constexpr int ALD = 72;                  // padded row: (8g+2q) banks
constexpr int ATILE = 64 * ALD;          // 4608 floats
constexpr int ASMEM = (5 * ATILE + 128) * 4;   // 92672 bytes

__global__ __launch_bounds__(128)
void attn_mma_kernel(const float* __restrict__ Qg, const float* __restrict__ Kg,
                     const float* __restrict__ Vg, const float* __restrict__ maskb,
                     float* __restrict__ O) {
    extern __shared__ float sm[];
    const uint32_t sb = smem_u32(sm);
    const int qb = blockIdx.x, hd = blockIdx.y, b = blockIdx.z;
    const int tid = threadIdx.x, wid = tid >> 5, lane = tid & 31;
    const int g = lane >> 2, q = lane & 3;
    const int wr = wid * 16;
    const int pc = (q & 1) * 4 + (q >> 1);    // sigma(2q)

    const size_t basekv = (size_t)(b * E) * D + hd * DH;

    auto load_kv = [&](int buf, int i) {
        const float* Kp = Kg + basekv + (size_t)(i * 64) * D;
        const float* Vp = Vg + basekv + (size_t)(i * 64) * D;
        const uint32_t sK = sb + (uint32_t)((1 + buf) * ATILE) * 4;
        const uint32_t sV = sb + (uint32_t)((3 + buf) * ATILE) * 4;
#pragma unroll
        for (int j = 0; j < 8; j++) {
            const int ch = j * 128 + tid;          // 1024 chunks: 64 rows x 16
            const int r = ch >> 4, c4 = ch & 15;
            const uint32_t off = (uint32_t)(r * ALD + c4 * 4) * 4;
            cpasync16(sK + off, Kp + (size_t)r * D + c4 * 4);
            cpasync16(sV + off, Vp + (size_t)r * D + c4 * 4);
        }
        if (tid < 16)
            cpasync16(sb + (uint32_t)(5 * ATILE + buf * 64 + tid * 4) * 4,
                      maskb + b * E + i * 64 + tid * 4);
        CP_COMMIT();
    };
    load_kv(0, 0);
    load_kv(1, 1);

    // Q tile (pre-scaled by 0.125 = 2^-3, exact on tf32 values) -> sQP
    const size_t baseq = ((size_t)(b * E) + qb * 64) * D + hd * DH;
#pragma unroll
    for (int j = 0; j < 8; j++) {
        const int ch = j * 128 + tid;
        const int r = ch >> 4, c4 = ch & 15;
        float4 v = *(const float4*)(Qg + baseq + (size_t)r * D + c4 * 4);
        v.x *= 0.125f; v.y *= 0.125f; v.z *= 0.125f; v.w *= 0.125f;
        *(float4*)(sm + r * ALD + c4 * 4) = v;
    }
    __syncthreads();

    // Q fragments in registers (own warp rows; permuted layout -> LDS.64)
    uint32_t qa[8][4];
#pragma unroll
    for (int ks = 0; ks < 8; ks++) {
        const int kb = ks * 8 + 2 * q;
        const float2 lo = *(const float2*)(&sm[(wr + g) * ALD + kb]);
        const float2 hi = *(const float2*)(&sm[(wr + g + 8) * ALD + kb]);
        qa[ks][0] = __float_as_uint(lo.x);
        qa[ks][1] = __float_as_uint(hi.x);
        qa[ks][2] = __float_as_uint(lo.y);
        qa[ks][3] = __float_as_uint(hi.y);
    }
    __syncwarp();

    float m0 = -1e30f, m1 = -1e30f, l0 = 0.f, l1 = 0.f;
    float oacc[8][4];
#pragma unroll
    for (int nf = 0; nf < 8; nf++)
#pragma unroll
        for (int k = 0; k < 4; k++) oacc[nf][k] = 0.f;

    float* Prow0 = sm + (wr + g) * ALD;        // P reuses the Q smem region
    float* Prow1 = sm + (wr + g + 8) * ALD;

    for (int i = 0; i < 16; i++) {
        const int buf = i & 1;
        if (i < 15) { CP_WAIT(1); } else { CP_WAIT(0); }
        __syncthreads();
        const float* sKb = sm + (1 + buf) * ATILE;
        const float* sVb = sm + (3 + buf) * ATILE;
        const float* kmb = sm + 5 * ATILE + buf * 64;

        // ---- scores: S = Q K^T (1x tf32, permuted LDS.64 B-frags) ----
        float sc[8][4];
#pragma unroll
        for (int nf = 0; nf < 8; nf++)
#pragma unroll
            for (int k = 0; k < 4; k++) sc[nf][k] = 0.f;
#pragma unroll
        for (int ks = 0; ks < 8; ks++) {
            const int kb = ks * 8 + 2 * q;
#pragma unroll
            for (int nf = 0; nf < 8; nf++) {
                const float2 bv = *(const float2*)(&sKb[(nf * 8 + g) * ALD + kb]);
                mma_tf32(sc[nf][0], sc[nf][1], sc[nf][2], sc[nf][3],
                         qa[ks][0], qa[ks][1], qa[ks][2], qa[ks][3],
                         __float_as_uint(bv.x), __float_as_uint(bv.y));
            }
        }

        // ---- mask + online softmax ----
        float mt0 = -1e30f, mt1 = -1e30f;
#pragma unroll
        for (int nf = 0; nf < 8; nf++) {
            const float mk0 = kmb[nf * 8 + 2 * q];
            const float mk1 = kmb[nf * 8 + 2 * q + 1];
            if (mk0 == 0.f) { sc[nf][0] = -1e9f; sc[nf][2] = -1e9f; }
            if (mk1 == 0.f) { sc[nf][1] = -1e9f; sc[nf][3] = -1e9f; }
            mt0 = fmaxf(mt0, fmaxf(sc[nf][0], sc[nf][1]));
            mt1 = fmaxf(mt1, fmaxf(sc[nf][2], sc[nf][3]));
        }
        mt0 = fmaxf(mt0, __shfl_xor_sync(0xFFFFFFFFu, mt0, 1));
        mt0 = fmaxf(mt0, __shfl_xor_sync(0xFFFFFFFFu, mt0, 2));
        mt1 = fmaxf(mt1, __shfl_xor_sync(0xFFFFFFFFu, mt1, 1));
        mt1 = fmaxf(mt1, __shfl_xor_sync(0xFFFFFFFFu, mt1, 2));
        const float mn0 = fmaxf(m0, mt0), mn1 = fmaxf(m1, mt1);
        const float al0 = __expf(m0 - mn0), al1 = __expf(m1 - mn1);
        m0 = mn0; m1 = mn1;

        float ps0 = 0.f, ps1 = 0.f;
#pragma unroll
        for (int nf = 0; nf < 8; nf++) {
            const float p0 = __expf(sc[nf][0] - mn0);
            const float p1 = __expf(sc[nf][1] - mn0);
            const float p2 = __expf(sc[nf][2] - mn1);
            const float p3 = __expf(sc[nf][3] - mn1);
            ps0 += p0 + p1; ps1 += p2 + p3;
            // store P permuted (key-dim sigma) for LDS.64 A-frag loads
            Prow0[nf * 8 + pc] = p0; Prow0[nf * 8 + pc + 2] = p1;
            Prow1[nf * 8 + pc] = p2; Prow1[nf * 8 + pc + 2] = p3;
            oacc[nf][0] *= al0; oacc[nf][1] *= al0;
            oacc[nf][2] *= al1; oacc[nf][3] *= al1;
        }
        ps0 += __shfl_xor_sync(0xFFFFFFFFu, ps0, 1);
        ps0 += __shfl_xor_sync(0xFFFFFFFFu, ps0, 2);
        ps1 += __shfl_xor_sync(0xFFFFFFFFu, ps1, 1);
        ps1 += __shfl_xor_sync(0xFFFFFFFFu, ps1, 2);
        l0 = l0 * al0 + ps0; l1 = l1 * al1 + ps1;
        __syncwarp();   // P visible within warp (A-frags read only own warp rows)

        // ---- O += P V (3x tf32: hi*hi + hi*lo + lo*hi) ----
#pragma unroll
        for (int ks = 0; ks < 8; ks++) {
            const int kb = ks * 8;
            const float2 f02 = *(const float2*)(&Prow0[kb + 2 * q]);   // f0,f2
            const float2 f13 = *(const float2*)(&Prow1[kb + 2 * q]);   // f1,f3
            uint32_t ah[4], alo[4];
            ah[0] = f2tf32(f02.x); alo[0] = f2tf32(f02.x - __uint_as_float(ah[0]));
            ah[1] = f2tf32(f13.x); alo[1] = f2tf32(f13.x - __uint_as_float(ah[1]));
            ah[2] = f2tf32(f02.y); alo[2] = f2tf32(f02.y - __uint_as_float(ah[2]));
            ah[3] = f2tf32(f13.y); alo[3] = f2tf32(f13.y - __uint_as_float(ah[3]));
#pragma unroll
            for (int nf = 0; nf < 8; nf++) {
                const float v0 = sVb[(kb + q) * ALD + nf * 8 + g];
                const float v1 = sVb[(kb + q + 4) * ALD + nf * 8 + g];
                const uint32_t vh0 = f2tf32(v0), vh1 = f2tf32(v1);
                const uint32_t vl0 = f2tf32(v0 - __uint_as_float(vh0));
                const uint32_t vl1 = f2tf32(v1 - __uint_as_float(vh1));
                mma_tf32(oacc[nf][0], oacc[nf][1], oacc[nf][2], oacc[nf][3],
                         ah[0], ah[1], ah[2], ah[3], vh0, vh1);
                mma_tf32(oacc[nf][0], oacc[nf][1], oacc[nf][2], oacc[nf][3],
                         ah[0], ah[1], ah[2], ah[3], vl0, vl1);
                mma_tf32(oacc[nf][0], oacc[nf][1], oacc[nf][2], oacc[nf][3],
                         alo[0], alo[1], alo[2], alo[3], vh0, vh1);
            }
        }
        __syncthreads();              // everyone done with this K/V buffer
        if (i + 2 < 16) load_kv(buf, i + 2);
    }

    // O: tf32-rounded + dh-permuted (feeds the WO GEMM contraction)
    const float il0 = 1.f / l0, il1 = 1.f / l1;
    float* Op0 = O + ((size_t)(b * E) + qb * 64 + wr + g) * D + hd * DH;
    float* Op1 = Op0 + (size_t)8 * D;
#pragma unroll
    for (int nf = 0; nf < 8; nf++) {
        const int cb = nf * 8;
        Op0[cb + pc]     = roundtf(oacc[nf][0] * il0);
        Op0[cb + pc + 2] = roundtf(oacc[nf][1] * il0);
        Op1[cb + pc]     = roundtf(oacc[nf][2] * il1);
        Op1[cb + pc + 2] = roundtf(oacc[nf][3] * il1);
    }
}

// ======== weight transposes: [K,N] -> [N,K], tf32-rounded, k-permuted =======
// A: 16 DxD slices (wq/wk/wv interleaved per layer into OFF_QKV, then wo)
__global__ void transposeA_kernel(const float* __restrict__ wq, const float* __restrict__ wk,
                                  const float* __restrict__ wv, const float* __restrict__ wo,
                                  float* __restrict__ wT) {
    __shared__ float t[32][33];
    const int z = blockIdx.z;
    const float* ip;
    float* op;
    if (z < 12) {
        const int l = z / 3, w = z % 3;
        ip = (w == 0 ? wq : (w == 1 ? wk : wv)) + (size_t)l * D * D;
        op = wT + OFF_QKV + (size_t)l * 3 * D * D + (size_t)w * D * D;
    } else {
        ip = wo + (size_t)(z - 12) * D * D;
        op = wT + OFF_OT + (size_t)(z - 12) * D * D;
    }
    const int n0 = blockIdx.x * 32, k0 = blockIdx.y * 32;
    const int tx = threadIdx.x, ty = threadIdx.y;   // 32 x 8
#pragma unroll
    for (int j = 0; j < 32; j += 8) t[ty + j][tx] = ip[(size_t)(k0 + ty + j) * D + n0 + tx];
    __syncthreads();
    const int k = k0 + tx;
    const int kp = (k & ~7) | (((k & 3) << 1) | ((k >> 2) & 1));
#pragma unroll
    for (int j = 0; j < 32; j += 8)
        op[(size_t)(n0 + ty + j) * D + kp] = roundtf(t[tx][ty + j]);
}

// B: w1 (K=D,N=F) z<4 ; w2 (K=F,N=D) z>=4. grid (64,16,8).
__global__ void transposeB_kernel(const float* __restrict__ w1, const float* __restrict__ w2,
                                  float* __restrict__ wT) {
    __shared__ float t[32][33];
    const int z = blockIdx.z;
    const float* ip;
    float* op;
    int Kd, Nd, n0, k0;
    if (z < 4) {
        ip = w1 + (size_t)z * D * F; op = wT + OFF_W1T + (size_t)z * D * F;
        Kd = D; Nd = F; n0 = blockIdx.x * 32; k0 = blockIdx.y * 32;
    } else {
        ip = w2 + (size_t)(z - 4) * F * D; op = wT + OFF_W2T + (size_t)(z - 4) * F * D;
        Kd = F; Nd = D; n0 = blockIdx.y * 32; k0 = blockIdx.x * 32;
    }
    const int tx = threadIdx.x, ty = threadIdx.y;
#pragma unroll
    for (int j = 0; j < 32; j += 8) t[ty + j][tx] = ip[(size_t)(k0 + ty + j) * Nd + n0 + tx];
    __syncthreads();
    const int k = k0 + tx;
    const int kp = (k & ~7) | (((k & 3) << 1) | ((k >> 2) & 1));
#pragma unroll
    for (int j = 0; j < 32; j += 8)
        op[(size_t)(n0 + ty + j) * Kd + kp] = roundtf(t[tx][ty + j]);
}

// ---------------- event extraction ----------------
__global__ void build_events_kernel(const float* __restrict__ x,
                                    float* __restrict__ rows,
                                    float* __restrict__ maskb) {
    const int b = blockIdx.x;
    const int tid = threadIdx.x;                 // 256 threads
    __shared__ unsigned char sx[T];
    __shared__ int partial[256];

    for (int i = tid; i < E * 11; i += 256) rows[(size_t)b * E * 11 + i] = 0.f;
    for (int i = tid; i < E; i += 256) maskb[b * E + i] = 0.f;

    const float* xb = x + (size_t)b * T * C;
    for (int t = tid; t < T; t += 256) {
        unsigned v = 0;
#pragma unroll
        for (int c = 0; c < C; c++) v |= (xb[(size_t)t * C + c] > 0.5f) ? (1u << c) : 0u;
        sx[t] = (unsigned char)v;
    }
    __syncthreads();

    const int t0 = tid * 16;
    unsigned char prev = (t0 == 0) ? (unsigned char)(~sx[0]) : sx[t0 - 1];
    unsigned char smloc[16];
    int cnt = 0;
#pragma unroll
    for (int i = 0; i < 16; i++) {
        unsigned char cur = sx[t0 + i];
        smloc[i] = (unsigned char)(cur ^ prev);
        prev = cur;
        cnt += __popc((unsigned)smloc[i]);
    }
    partial[tid] = cnt;
    __syncthreads();
    if (tid == 0) {
        int run = 0;
        for (int i = 0; i < 256; i++) { int tmp = partial[i]; partial[i] = run; run += tmp; }
    }
    __syncthreads();

    int e = partial[tid];
    for (int i = 0; i < 16; i++) {
        const int t = t0 + i;
        unsigned m = smloc[i];
        while (m) {
            const int c = __ffs(m) - 1;
            m &= (m - 1);
            if (e < E) {
                const int v = (sx[t] >> c) & 1;
                int tt = t + 1;
                while (tt < T && (((sx[tt] >> c) & 1) == v)) tt++;
                float* r = rows + ((size_t)b * E + e) * 11;
                r[c] = 1.f;
                r[8] = (float)v;
                r[9] = (float)t / (float)(T - 1);
                r[10] = (float)(tt - t) / (float)T;
                maskb[b * E + e] = 1.f;
            }
            e++;
        }
    }
}

// ---------------- input projection (K=11) ----------------
__global__ void proj_kernel(const float* __restrict__ rows,
                            const float* __restrict__ pw,
                            const float* __restrict__ pb,
                            float* __restrict__ h) {
    const int be = blockIdx.x;
    __shared__ float r[11];
    if (threadIdx.x < 11) r[threadIdx.x] = rows[(size_t)be * 11 + threadIdx.x];
    __syncthreads();
    const int d = threadIdx.x;
    float acc = pb[d];
#pragma unroll
    for (int j = 0; j < 11; j++) acc += r[j] * pw[j * D + d];
    h[(size_t)be * D + d] = acc;
}

// -------- LayerNorm: warp per row; PERM -> tf32-rounded + k-permuted --------
template <bool PERM>
__global__ __launch_bounds__(256)
void ln_kernel(const float* __restrict__ h, const float* __restrict__ g,
               const float* __restrict__ bb, float* __restrict__ z) {
    const int row = blockIdx.x * 8 + (threadIdx.x >> 5);
    const int lane = threadIdx.x & 31;
    const float* hr = h + (size_t)row * D;

    float4 v[4];
    float s = 0.f, s2 = 0.f;
#pragma unroll
    for (int i = 0; i < 4; i++) {
        v[i] = *(const float4*)(hr + i * 128 + lane * 4);
        s += v[i].x + v[i].y + v[i].z + v[i].w;
        s2 += v[i].x * v[i].x + v[i].y * v[i].y + v[i].z * v[i].z + v[i].w * v[i].w;
    }
#pragma unroll
    for (int o = 16; o; o >>= 1) {
        s += __shfl_xor_sync(0xFFFFFFFFu, s, o);
        s2 += __shfl_xor_sync(0xFFFFFFFFu, s2, o);
    }
    const float mean = s * (1.f / D);
    const float var = s2 * (1.f / D) - mean * mean;
    const float inv = rsqrtf(var + 1e-5f);

    float* zr = z + (size_t)row * D;
#pragma unroll
    for (int i = 0; i < 4; i++) {
        const int cc = i * 128 + lane * 4;
        const float4 gg = *(const float4*)(g + cc);
        const float4 bv = *(const float4*)(bb + cc);
        float4 o;
        o.x = (v[i].x - mean) * inv * gg.x + bv.x;
        o.y = (v[i].y - mean) * inv * gg.y + bv.y;
        o.z = (v[i].z - mean) * inv * gg.z + bv.z;
        o.w = (v[i].w - mean) * inv * gg.w + bv.w;
        if (PERM) {
            const int base = (cc & ~7) + ((cc >> 2) & 1);
            zr[base + 0] = roundtf(o.x);
            zr[base + 2] = roundtf(o.y);
            zr[base + 4] = roundtf(o.z);
            zr[base + 6] = roundtf(o.w);
        } else {
            *(float4*)(zr + cc) = o;
        }
    }
}

// ---------------- masked mean pooling ----------------
__global__ void pool_kernel(const float* __restrict__ z,
                            const float* __restrict__ maskb,
                            float* __restrict__ out) {
    const int b = blockIdx.x;
    const int d = threadIdx.x;
    float s = 0.f, cnt = 0.f;
    for (int e = 0; e < E; e++) {
        const float mk = maskb[b * E + e];
        cnt += mk;
        s += z[((size_t)b * E + e) * D + d] * mk;
    }
    out[(size_t)b * D + d] = s / fmaxf(cnt, 1.f);
}

// ---------------- launch ----------------
extern "C" void kernel_launch(void* const* d_in, const int* in_sizes, int n_in,
                              void* d_out, int out_size) {
    const float* x      = (const float*)d_in[0];
    const float* proj_w = (const float*)d_in[1];
    const float* proj_b = (const float*)d_in[2];
    const float* wq     = (const float*)d_in[3];
    const float* wk     = (const float*)d_in[4];
    const float* wv     = (const float*)d_in[5];
    const float* wo     = (const float*)d_in[6];
    const float* ln1_g  = (const float*)d_in[7];
    const float* ln1_b  = (const float*)d_in[8];
    const float* w1     = (const float*)d_in[9];
    const float* b1     = (const float*)d_in[10];
    const float* w2     = (const float*)d_in[11];
    const float* b2     = (const float*)d_in[12];
    const float* ln2_g  = (const float*)d_in[13];
    const float* ln2_b  = (const float*)d_in[14];
    const float* lnf_g  = (const float*)d_in[15];
    const float* lnf_b  = (const float*)d_in[16];
    float* out = (float*)d_out;

    float *p_rows, *p_mask, *p_h, *p_z, *p_q, *p_k, *p_v, *p_o, *p_f, *p_wT;
    cudaGetSymbolAddress((void**)&p_rows, g_rows);
    cudaGetSymbolAddress((void**)&p_mask, g_mask);
    cudaGetSymbolAddress((void**)&p_h, g_h);
    cudaGetSymbolAddress((void**)&p_z, g_z);
    cudaGetSymbolAddress((void**)&p_q, g_q);
    cudaGetSymbolAddress((void**)&p_k, g_k);
    cudaGetSymbolAddress((void**)&p_v, g_v);
    cudaGetSymbolAddress((void**)&p_o, g_o);
    cudaGetSymbolAddress((void**)&p_f, g_f);
    cudaGetSymbolAddress((void**)&p_wT, g_wT);

    static bool attr_set = false;
    if (!attr_set) {
        cudaFuncSetAttribute(tgemm_kernel<false, false, false, true, true>,  cudaFuncAttributeMaxDynamicSharedMemorySize, GSMEM);
        cudaFuncSetAttribute(tgemm_kernel<false, false, true, false, false>, cudaFuncAttributeMaxDynamicSharedMemorySize, GSMEM);
        cudaFuncSetAttribute(tgemm_kernel<true, true, false, true, false>,   cudaFuncAttributeMaxDynamicSharedMemorySize, GSMEM);
        cudaFuncSetAttribute(tgemm_kernel<true, false, true, false, false>,  cudaFuncAttributeMaxDynamicSharedMemorySize, GSMEM);
        cudaFuncSetAttribute(attn_mma_kernel, cudaFuncAttributeMaxDynamicSharedMemorySize, ASMEM);
        attr_set = true;
    }

    const int M = B * E;                       // 8192
    const dim3 gQKV(12, M / 128);              // fused QKV: N=1536
    const dim3 gD(D / 128, M / 128);           // (4, 64)
    const dim3 gF(F / 128, M / 128);           // (16, 64)
    const dim3 tb(32, 8);

    // launch order: ncu (-s 5 -c 1) profiles launch #5 = the first QKV tgemm
    transposeA_kernel<<<dim3(16, 16, 16), tb>>>(wq, wk, wv, wo, p_wT);   // 0
    transposeB_kernel<<<dim3(64, 16, 8), tb>>>(w1, w2, p_wT);            // 1
    build_events_kernel<<<B, 256>>>(x, p_rows, p_mask);                  // 2
    proj_kernel<<<M, 512>>>(p_rows, proj_w, proj_b, p_h);                // 3

    for (int l = 0; l < NL; l++) {
        const float* qkvT = p_wT + OFF_QKV + (size_t)l * 3 * D * D;
        const float* woT  = p_wT + OFF_OT  + (size_t)l * D * D;
        const float* w1T  = p_wT + OFF_W1T + (size_t)l * D * F;
        const float* w2T  = p_wT + OFF_W2T + (size_t)l * D * F;

        ln_kernel<true><<<M / 8, 256>>>(p_h, ln1_g + l * D, ln1_b + l * D, p_z);   // 4
        tgemm_kernel<false, false, false, true, true><<<gQKV, 128, GSMEM>>>(
            p_z, qkvT, nullptr, p_q, p_k, p_v, M, 3 * D, D);                       // 5 <- profiled
        attn_mma_kernel<<<dim3(E / 64, NH, B), 128, ASMEM>>>(p_q, p_k, p_v, p_mask, p_o);
        tgemm_kernel<false, false, true, false, false><<<gD, 128, GSMEM>>>(
            p_o, woT, nullptr, p_h, nullptr, nullptr, M, D, D);

        ln_kernel<true><<<M / 8, 256>>>(p_h, ln2_g + l * D, ln2_b + l * D, p_z);
        tgemm_kernel<true, true, false, true, false><<<gF, 128, GSMEM>>>(
            p_z, w1T, b1 + (size_t)l * F, p_f, nullptr, nullptr, M, F, D);
        tgemm_kernel<true, false, true, false, false><<<gD, 128, GSMEM>>>(
            p_f, w2T, b2 + (size_t)l * D, p_h, nullptr, nullptr, M, D, F);
    }

    ln_kernel<false><<<M / 8, 256>>>(p_h, lnf_g, lnf_b, p_z);
    pool_kernel<<<B, D>>>(p_z, p_mask, out);
}